// round 13
// baseline (speedup 1.0000x reference)
#include <cuda_runtime.h>
#include <cuda_bf16.h>
#include <math.h>
#include <stdint.h>

// Problem constants
#define Bn   32
#define Tn   512
#define DEMB 768
#define NSRC 10
#define Hn   16
#define On   16
#define BT   (Bn*Tn)          // 16384
#define NTRANS 256            // H*H
#define NEMISS 2560           // NSRC*H*O

// ---------------- scratch (static device memory; no allocation) ----------------
__device__ __align__(16) float g_logev[BT*Hn];
__device__ __align__(16) float g_alpha[BT*Hn];
__device__ __align__(16) float g_beta [BT*Hn];
__device__ __align__(16) float g_emis [BT];
__device__ __align__(16) float g_tran [BT];
__device__ __align__(16) float g_prior[Bn];
__device__ __align__(16) float g_lsp  [Hn];
__device__ __align__(16) float g_mix_trans[NTRANS];
__device__ __align__(16) float g_mix_emiss[NEMISS];
__device__ __align__(16) float g_ltr_scratch[(size_t)BT * NTRANS];
__device__ __align__(16) float g_lem_scratch[(size_t)BT * NEMISS];

// bf16 split operands for tensor-core GEMM
__device__ __align__(16) __nv_bfloat16 g_Ahi[(size_t)BT*DEMB];
__device__ __align__(16) __nv_bfloat16 g_Alo[(size_t)BT*DEMB];
__device__ __align__(16) __nv_bfloat16 g_Bthi[(size_t)NTRANS*DEMB];
__device__ __align__(16) __nv_bfloat16 g_Btlo[(size_t)NTRANS*DEMB];
__device__ __align__(16) __nv_bfloat16 g_Behi[(size_t)NEMISS*DEMB];
__device__ __align__(16) __nv_bfloat16 g_Belo[(size_t)NEMISS*DEMB];

// ---------------- helpers ----------------
__device__ __forceinline__ uint32_t smem_to_u32(const void* p) {
    uint32_t a;
    asm("{ .reg .u64 t; cvta.to.shared.u64 t, %1; cvt.u32.u64 %0, t; }" : "=r"(a) : "l"(p));
    return a;
}
#define CP_ASYNC16(saddr, gptr) \
    asm volatile("cp.async.cg.shared.global [%0], [%1], 16;" :: "r"(saddr), "l"(gptr))
#define CP_COMMIT() asm volatile("cp.async.commit_group;" ::: "memory")
#define LDSM4(r0,r1,r2,r3, addr) \
    asm volatile("ldmatrix.sync.aligned.m8n8.x4.shared.b16 {%0,%1,%2,%3}, [%4];" \
        : "=r"(r0),"=r"(r1),"=r"(r2),"=r"(r3) : "r"(addr))

__device__ __forceinline__ void mma16816(float* c, const uint32_t* a, uint32_t b0, uint32_t b1) {
    asm volatile(
        "mma.sync.aligned.m16n8k16.row.col.f32.bf16.bf16.f32 "
        "{%0,%1,%2,%3}, {%4,%5,%6,%7}, {%8,%9}, {%0,%1,%2,%3};"
        : "+f"(c[0]), "+f"(c[1]), "+f"(c[2]), "+f"(c[3])
        : "r"(a[0]), "r"(a[1]), "r"(a[2]), "r"(a[3]), "r"(b0), "r"(b1));
}

__device__ __forceinline__ void split_bf16(float x, __nv_bfloat16& h, __nv_bfloat16& l) {
    h = __float2bfloat16_rn(x);
    l = __float2bfloat16_rn(x - __bfloat162float(h));
}

// ---------------- merged prep: emb split + weight transpose/split + tables ------
#define NB_EMB ((BT*DEMB/4 + 255)/256)                    // 12288
#define NB_W   (((NTRANS+NEMISS)*DEMB + 255)/256)         // 8448
__global__ __launch_bounds__(256)
void prep_kernel(const float* __restrict__ emb,
                 const float* __restrict__ Wt, const float* __restrict__ We,
                 const float* __restrict__ ut, const float* __restrict__ ue,
                 const float* __restrict__ sp) {
    int blk = blockIdx.x;
    int tid = threadIdx.x;
    if (blk < NB_EMB) {
        int i = blk * 256 + tid;
        const int N4 = (BT * DEMB) / 4;
        if (i < N4) {
            float4 v = ((const float4*)emb)[i];
            __nv_bfloat16 h0,h1,h2,h3,l0,l1,l2,l3;
            split_bf16(v.x,h0,l0); split_bf16(v.y,h1,l1);
            split_bf16(v.z,h2,l2); split_bf16(v.w,h3,l3);
            __nv_bfloat162* ph = (__nv_bfloat162*)(g_Ahi + (size_t)i*4);
            __nv_bfloat162* pl = (__nv_bfloat162*)(g_Alo + (size_t)i*4);
            ph[0] = __nv_bfloat162(h0,h1); ph[1] = __nv_bfloat162(h2,h3);
            pl[0] = __nv_bfloat162(l0,l1); pl[1] = __nv_bfloat162(l2,l3);
        }
    } else if (blk < NB_EMB + NB_W) {
        int idx = (blk - NB_EMB) * 256 + tid;
        const int NT = NTRANS * DEMB;
        const int NE = NEMISS * DEMB;
        if (idx < NT) {
            int n = idx / DEMB, k = idx % DEMB;
            float x = Wt[(size_t)k * NTRANS + n];
            split_bf16(x, g_Bthi[idx], g_Btlo[idx]);
        } else if (idx < NT + NE) {
            int j = idx - NT;
            int n = j / DEMB, k = j % DEMB;
            int s = n >> 8, e = n & 255;
            float x = We[((size_t)s * DEMB + k) * 256 + e];
            split_bf16(x, g_Behi[j], g_Belo[j]);
        }
    } else {
        if (tid < 16) {
            float v[16]; float m = -1e30f;
            #pragma unroll
            for (int o = 0; o < 16; o++) { v[o] = ut[tid*16+o]; m = fmaxf(m, v[o]); }
            float s = 0.f;
            #pragma unroll
            for (int o = 0; o < 16; o++) s += expf(v[o]-m);
            float inv = 0.5f / s;
            #pragma unroll
            for (int o = 0; o < 16; o++) g_mix_trans[tid*16+o] = expf(v[o]-m) * inv;
        }
        if (tid >= 32 && tid < 32 + NSRC*Hn) {
            int r = tid - 32;
            float v[16]; float m = -1e30f;
            #pragma unroll
            for (int o = 0; o < 16; o++) { v[o] = ue[r*16+o]; m = fmaxf(m, v[o]); }
            float s = 0.f;
            #pragma unroll
            for (int o = 0; o < 16; o++) s += expf(v[o]-m);
            float inv = 0.5f / s;
            #pragma unroll
            for (int o = 0; o < 16; o++) g_mix_emiss[r*16+o] = expf(v[o]-m) * inv;
        }
        if (tid == 255) {
            float m = -1e30f;
            for (int h = 0; h < 16; h++) m = fmaxf(m, sp[h]);
            float s = 0.f;
            for (int h = 0; h < 16; h++) s += expf(sp[h]-m);
            float lse = m + logf(s);
            for (int h = 0; h < 16; h++) g_lsp[h] = sp[h] - lse;
        }
    }
}

// ---------------- merged HMMA GEMM + fused softmax/log-mix epilogue ----------------
// R9 tiling (128x128, BK=32, 8 warps, lb(256,2)) + pass-major MMA order.
#define BMH 128
#define BNH 128
#define BKH 32
#define NCH (DEMB/BKH)        // 24
#define ASTR 80
#define STG_A_HI 0
#define STG_A_LO 10240
#define STG_B_HI 20480
#define STG_B_LO 30720
#define STG_BYTES 40960
#define HSMEM (2*STG_BYTES)   // 81920
#define YEM 20

__global__ __launch_bounds__(256, 2)
void hmma_gemm_kernel(const float* __restrict__ bias_t, const float* __restrict__ bias_e,
                      float* __restrict__ out_t, float* __restrict__ out_e) {
    extern __shared__ __align__(128) char smem[];
    const int tid = threadIdx.x, wid = tid >> 5, lane = tid & 31;
    const int warp_m = wid >> 2, warp_n = wid & 3;
    const int m0 = blockIdx.x * BMH;
    const bool emiss = (blockIdx.y < YEM);
    const int n0 = emiss ? blockIdx.y * BNH : (blockIdx.y - YEM) * BNH;
    const int ncols = emiss ? NEMISS : NTRANS;
    const __nv_bfloat16* __restrict__ Bh = emiss ? g_Behi : g_Bthi;
    const __nv_bfloat16* __restrict__ Bl = emiss ? g_Belo : g_Btlo;
    const float* __restrict__ mixp = emiss ? g_mix_emiss : g_mix_trans;
    const float* __restrict__ bias = emiss ? bias_e : bias_t;
    float* __restrict__ out = emiss ? out_e : out_t;
    const uint32_t sbase = smem_to_u32(smem);

    float bia[8], mx[8];
    {
        int cbase = n0 + warp_n*32 + (lane & 3)*2;
        #pragma unroll
        for (int p = 0; p < 2; p++)
            #pragma unroll
            for (int sel = 0; sel < 2; sel++)
                #pragma unroll
                for (int j = 0; j < 2; j++) {
                    int col = cbase + p*16 + sel*8 + j;
                    bia[p*4+sel*2+j] = bias[col];
                    mx [p*4+sel*2+j] = mixp[col];
                }
    }

    float c[4][4][4];
    #pragma unroll
    for (int a = 0; a < 4; a++)
        #pragma unroll
        for (int b = 0; b < 4; b++)
            #pragma unroll
            for (int q = 0; q < 4; q++) c[a][b][q] = 0.f;

    auto load_chunk = [&](int kc, int stage) {
        const int k0 = kc * BKH;
        uint32_t sm = sbase + stage * STG_BYTES;
        #pragma unroll
        for (int i = 0; i < 2; i++) {
            int seg = i*256 + tid;
            int r = seg >> 2, s = seg & 3;
            size_t goffA = (size_t)(m0 + r) * DEMB + k0 + s*8;
            size_t goffB = (size_t)(n0 + r) * DEMB + k0 + s*8;
            uint32_t soff = (uint32_t)(r * ASTR + s * 16);
            CP_ASYNC16(sm + STG_A_HI + soff, g_Ahi + goffA);
            CP_ASYNC16(sm + STG_A_LO + soff, g_Alo + goffA);
            CP_ASYNC16(sm + STG_B_HI + soff, Bh + goffB);
            CP_ASYNC16(sm + STG_B_LO + soff, Bl + goffB);
        }
        CP_COMMIT();
    };

    auto compute_chunk = [&](int stage) {
        uint32_t sm = sbase + stage * STG_BYTES;
        #pragma unroll
        for (int kk = 0; kk < BKH; kk += 16) {
            uint32_t ah[4][4], al[4][4], bh[2][4], bl[2][4];
            {
                int ar = warp_m*64 + (lane & 15);
                int ac = kk + ((lane >> 4) << 3);
                uint32_t ab = sm + (uint32_t)(ar * ASTR + ac * 2);
                #pragma unroll
                for (int mi = 0; mi < 4; mi++) {
                    LDSM4(ah[mi][0],ah[mi][1],ah[mi][2],ah[mi][3], ab + STG_A_HI + mi*16*ASTR);
                    LDSM4(al[mi][0],al[mi][1],al[mi][2],al[mi][3], ab + STG_A_LO + mi*16*ASTR);
                }
            }
            {
                int br = warp_n*32 + (lane & 7) + ((lane >> 3) & 1)*8;
                int bc = kk + ((lane >> 4) << 3);
                uint32_t bb = sm + (uint32_t)(br * ASTR + bc * 2);
                #pragma unroll
                for (int p = 0; p < 2; p++) {
                    LDSM4(bh[p][0],bh[p][1],bh[p][2],bh[p][3], bb + STG_B_HI + p*16*ASTR);
                    LDSM4(bl[p][0],bl[p][1],bl[p][2],bl[p][3], bb + STG_B_LO + p*16*ASTR);
                }
            }
            // pass-major order: 16 independent MMAs between accumulator reuses
            #pragma unroll
            for (int mi = 0; mi < 4; mi++)
                #pragma unroll
                for (int p = 0; p < 2; p++) {
                    mma16816(c[mi][2*p+0], ah[mi], bh[p][0], bh[p][2]);
                    mma16816(c[mi][2*p+1], ah[mi], bh[p][1], bh[p][3]);
                }
            #pragma unroll
            for (int mi = 0; mi < 4; mi++)
                #pragma unroll
                for (int p = 0; p < 2; p++) {
                    mma16816(c[mi][2*p+0], ah[mi], bl[p][0], bl[p][2]);
                    mma16816(c[mi][2*p+1], ah[mi], bl[p][1], bl[p][3]);
                }
            #pragma unroll
            for (int mi = 0; mi < 4; mi++)
                #pragma unroll
                for (int p = 0; p < 2; p++) {
                    mma16816(c[mi][2*p+0], al[mi], bh[p][0], bh[p][2]);
                    mma16816(c[mi][2*p+1], al[mi], bh[p][1], bh[p][3]);
                }
        }
    };

    load_chunk(0, 0);
    for (int kc = 0; kc < NCH; kc++) {
        if (kc + 1 < NCH) {
            load_chunk(kc + 1, (kc + 1) & 1);
            asm volatile("cp.async.wait_group 1;" ::: "memory");
        } else {
            asm volatile("cp.async.wait_group 0;" ::: "memory");
        }
        __syncthreads();
        compute_chunk(kc & 1);
        __syncthreads();
    }

    #pragma unroll
    for (int mi = 0; mi < 4; mi++) {
        int rA = m0 + warp_m*64 + mi*16 + (lane >> 2);
        #pragma unroll
        for (int p = 0; p < 2; p++) {
            #pragma unroll
            for (int half = 0; half < 2; half++) {
                float v0 = c[mi][2*p+0][half*2+0] + bia[p*4+0];
                float v1 = c[mi][2*p+0][half*2+1] + bia[p*4+1];
                float v2 = c[mi][2*p+1][half*2+0] + bia[p*4+2];
                float v3 = c[mi][2*p+1][half*2+1] + bia[p*4+3];
                float m = fmaxf(fmaxf(v0, v1), fmaxf(v2, v3));
                m = fmaxf(m, __shfl_xor_sync(0xffffffffu, m, 1));
                m = fmaxf(m, __shfl_xor_sync(0xffffffffu, m, 2));
                float e0 = __expf(v0-m), e1 = __expf(v1-m), e2 = __expf(v2-m), e3 = __expf(v3-m);
                float s = e0 + e1 + e2 + e3;
                s += __shfl_xor_sync(0xffffffffu, s, 1);
                s += __shfl_xor_sync(0xffffffffu, s, 2);
                float inv = 0.5f / s;
                int row = rA + half*8;
                float* orow = out + (size_t)row * ncols + n0 + warp_n*32 + p*16 + (lane & 3)*2;
                orow[0] = __logf(mx[p*4+0] + e0*inv);
                orow[1] = __logf(mx[p*4+1] + e1*inv);
                orow[8] = __logf(mx[p*4+2] + e2*inv);
                orow[9] = __logf(mx[p*4+3] + e3*inv);
            }
        }
    }
}

// ---------------- emission evidence (lane-parallel over o, coalesced) ----------
__global__ __launch_bounds__(256) void logev_kernel(const float* __restrict__ obs,
                                                    const float* __restrict__ lem) {
    int bt = blockIdx.x;
    int tid = threadIdx.x, wid = tid >> 5, lane = tid & 31;
    __shared__ float slog[NSRC][16];
    __shared__ float part[NSRC][16];
    __shared__ float sobs[NSRC][16];
    __shared__ int   lbs[NSRC];
    __shared__ int   entity;

    if (tid < NSRC*16) {
        int s = tid >> 4, o = tid & 15;
        sobs[s][o] = obs[(size_t)bt * NSRC * 16 + tid];
    }
    __syncthreads();
    if (tid < NSRC) {
        int am = 0; float bv = sobs[tid][0];
        for (int k = 1; k < 16; k++) if (sobs[tid][k] > bv) { bv = sobs[tid][k]; am = k; }
        lbs[tid] = am;
    }
    __syncthreads();
    if (tid == 0) { int su = 0; for (int q = 0; q < NSRC; q++) su += lbs[q]; entity = (su > 0); }
    __syncthreads();
    if (tid < NSRC*16) {
        int s = tid >> 4, o = tid & 15;
        float val;
        if (entity && lbs[s] == 0) val = (o == 0) ? 0.01f : (0.99f/16.0f);
        else                       val = sobs[s][o];
        slog[s][o] = logf(val);
    }
    __syncthreads();

    const float* lbase = lem + (size_t)bt * NEMISS;
    int o = lane & 15;
    int hw = lane >> 4;
    #pragma unroll
    for (int it = 0; it < 10; it++) {
        int pi = wid*20 + it*2 + hw;     // 0..159
        int s = pi >> 4, h = pi & 15;
        float x = lbase[s*256 + h*16 + o] + slog[s][o];
        float m = x;
        #pragma unroll
        for (int d = 8; d; d >>= 1) m = fmaxf(m, __shfl_xor_sync(0xffffffffu, m, d));
        float e = __expf(x - m);
        #pragma unroll
        for (int d = 8; d; d >>= 1) e += __shfl_xor_sync(0xffffffffu, e, d);
        if (o == 0) part[s][h] = m + __logf(e);
    }
    __syncthreads();
    if (tid < 16) {
        float t = 0.f;
        #pragma unroll
        for (int q = 0; q < NSRC; q++) t += part[q][tid];
        g_logev[bt*16 + tid] = t;
    }
}

// ---------------- warp-per-chain scans (no block barriers) ----------------
__global__ __launch_bounds__(32) void scan_kernel(const float* __restrict__ ltr) {
    const unsigned FULL = 0xffffffffu;
    int lane = threadIdx.x;
    int b = blockIdx.x & 31;
    int j = lane & 15, half = lane >> 4;
    const float* lt_base = ltr + (size_t)b * Tn * 256;

    if (blockIdx.x < 32) {
        float carry = g_lsp[j] + g_logev[(b*Tn)*16 + j];
        if (lane < 16) g_alpha[(b*Tn)*16 + lane] = carry;
        float tr[8];
        #pragma unroll
        for (int k = 0; k < 8; k++) tr[k] = lt_base[(size_t)256 + (half*8+k)*16 + j];
        float sev = g_logev[(b*Tn + 1)*16 + j];
        for (int t = 1; t < Tn; t++) {
            float ntr[8], nev = 0.f;
            if (t + 1 < Tn) {
                #pragma unroll
                for (int k = 0; k < 8; k++)
                    ntr[k] = lt_base[(size_t)(t+1)*256 + (half*8+k)*16 + j];
                nev = g_logev[(b*Tn + t+1)*16 + j];
            } else {
                #pragma unroll
                for (int k = 0; k < 8; k++) ntr[k] = 0.f;
            }
            float v[8];
            #pragma unroll
            for (int k = 0; k < 8; k++)
                v[k] = __shfl_sync(FULL, carry, half*8 + k) + tr[k];
            float m = fmaxf(fmaxf(fmaxf(v[0],v[1]), fmaxf(v[2],v[3])),
                            fmaxf(fmaxf(v[4],v[5]), fmaxf(v[6],v[7])));
            m = fmaxf(m, __shfl_xor_sync(FULL, m, 16));
            float e = 0.f;
            #pragma unroll
            for (int k = 0; k < 8; k++) e += __expf(v[k] - m);
            e += __shfl_xor_sync(FULL, e, 16);
            carry = sev + m + __logf(e);
            if (lane < 16) g_alpha[((size_t)b*Tn + t)*16 + lane] = carry;
            if ((t & 63) == 63) {
                float mm = carry;
                mm = fmaxf(mm, __shfl_xor_sync(FULL, mm, 1));
                mm = fmaxf(mm, __shfl_xor_sync(FULL, mm, 2));
                mm = fmaxf(mm, __shfl_xor_sync(FULL, mm, 4));
                mm = fmaxf(mm, __shfl_xor_sync(FULL, mm, 8));
                carry -= mm;
            }
            #pragma unroll
            for (int k = 0; k < 8; k++) tr[k] = ntr[k];
            sev = nev;
        }
    } else {
        int i = lane & 15;
        float carry = 0.f;
        if (lane < 16) g_beta[((size_t)b*Tn + Tn-1)*16 + lane] = 0.f;
        float tr[8];
        #pragma unroll
        for (int k = 0; k < 8; k++)
            tr[k] = lt_base[(size_t)(Tn-2)*256 + i*16 + half*8 + k];
        float sev = g_logev[(b*Tn + Tn-2)*16 + j];
        for (int t = Tn-2; t >= 0; t--) {
            float ntr[8], nev = 0.f;
            if (t > 0) {
                #pragma unroll
                for (int k = 0; k < 8; k++)
                    ntr[k] = lt_base[(size_t)(t-1)*256 + i*16 + half*8 + k];
                nev = g_logev[(b*Tn + t-1)*16 + j];
            } else {
                #pragma unroll
                for (int k = 0; k < 8; k++) ntr[k] = 0.f;
            }
            float cs = sev + carry;
            float v[8];
            #pragma unroll
            for (int k = 0; k < 8; k++)
                v[k] = tr[k] + __shfl_sync(FULL, cs, half*8 + k);
            float m = fmaxf(fmaxf(fmaxf(v[0],v[1]), fmaxf(v[2],v[3])),
                            fmaxf(fmaxf(v[4],v[5]), fmaxf(v[6],v[7])));
            m = fmaxf(m, __shfl_xor_sync(FULL, m, 16));
            float e = 0.f;
            #pragma unroll
            for (int k = 0; k < 8; k++) e += __expf(v[k] - m);
            e += __shfl_xor_sync(FULL, e, 16);
            carry = m + __logf(e);
            if (lane < 16) g_beta[((size_t)b*Tn + t)*16 + lane] = carry;
            #pragma unroll
            for (int k = 0; k < 8; k++) tr[k] = ntr[k];
            sev = nev;
        }
    }
}

// ---------------- gamma / xi / per-(b,t) likelihood terms ----------------
__global__ __launch_bounds__(256) void gx_kernel(const float* __restrict__ ltr,
                                                 const int* __restrict__ seqlen) {
    int bt = blockIdx.x, b = bt >> 9, t = bt & (Tn-1), tid = threadIdx.x;
    __shared__ float sa[16], sb[16], se[16], spa[16];
    __shared__ float sw[8];
    int len = seqlen[b];
    int tr = t + (Tn - len); if (tr >= Tn) tr -= Tn;
    if (tid < 16) {
        sa[tid]  = g_alpha[bt*16 + tid];
        sb[tid]  = g_beta[((size_t)b*Tn + tr)*16 + tid];
        se[tid]  = g_logev[bt*16 + tid];
        spa[tid] = (t > 0) ? g_alpha[(bt-1)*16 + tid] : 0.f;
    }
    __syncthreads();
    if (tid == 0) {
        float m = -1e30f;
        for (int h = 0; h < 16; h++) m = fmaxf(m, sa[h]+sb[h]);
        float s = 0.f;
        for (int h = 0; h < 16; h++) s += expf(sa[h]+sb[h]-m);
        float lse = m + logf(s);
        float emis = 0.f, pr = 0.f;
        for (int h = 0; h < 16; h++) {
            float g = expf(sa[h]+sb[h]-lse);
            emis += g * se[h]; pr += g * g_lsp[h];
        }
        g_emis[bt] = emis;
        if (t == 0) g_prior[b] = pr;
    }
    if (t == 0) { if (tid == 0) g_tran[bt] = 0.f; return; }

    float lt = ltr[(size_t)bt*256 + tid];
    float x = lt + spa[tid>>4] + se[tid&15] + sb[tid&15];

    float m = x;
    #pragma unroll
    for (int o = 16; o; o >>= 1) m = fmaxf(m, __shfl_xor_sync(0xffffffffu, m, o));
    if ((tid & 31) == 0) sw[tid>>5] = m;
    __syncthreads();
    m = sw[0];
    #pragma unroll
    for (int wq = 1; wq < 8; wq++) m = fmaxf(m, sw[wq]);
    __syncthreads();
    float e = expf(x - m);
    float s = e;
    #pragma unroll
    for (int o = 16; o; o >>= 1) s += __shfl_xor_sync(0xffffffffu, s, o);
    if ((tid & 31) == 0) sw[tid>>5] = s;
    __syncthreads();
    s = 0.f;
    #pragma unroll
    for (int wq = 0; wq < 8; wq++) s += sw[wq];
    __syncthreads();
    float norm = m + logf(s);
    float term = expf(x - norm) * lt;
    float ts = term;
    #pragma unroll
    for (int o = 16; o; o >>= 1) ts += __shfl_xor_sync(0xffffffffu, ts, o);
    if ((tid & 31) == 0) sw[tid>>5] = ts;
    __syncthreads();
    if (tid == 0) {
        float tot = 0.f;
        #pragma unroll
        for (int wq = 0; wq < 8; wq++) tot += sw[wq];
        g_tran[bt] = tot;
    }
}

// ---------------- final masked reduction -> ll ----------------
__global__ void fin_kernel(const int* __restrict__ seqlen, float* __restrict__ out) {
    __shared__ float sh[256];
    int tid = threadIdx.x;
    float acc = 0.f;
    for (int bt = tid; bt < BT; bt += 256) {
        int b = bt >> 9, t = bt & (Tn-1);
        int len = seqlen[b];
        if (t < len) {
            acc += g_emis[bt];
            if (t >= 1) acc += g_tran[bt];
        }
    }
    if (tid < Bn) acc += g_prior[tid];
    sh[tid] = acc;
    __syncthreads();
    for (int s = 128; s; s >>= 1) {
        if (tid < s) sh[tid] += sh[tid + s];
        __syncthreads();
    }
    if (tid == 0) out[0] = sh[0] / (float)Bn;
}

// ---------------- launch ----------------
extern "C" void kernel_launch(void* const* d_in, const int* in_sizes, int n_in,
                              void* d_out, int out_size) {
    const float* emb  = (const float*)d_in[0];
    const float* obs  = (const float*)d_in[1];
    const int*   slen = (const int*)  d_in[2];
    const float* Wt   = (const float*)d_in[3];
    const float* bt_  = (const float*)d_in[4];
    const float* We   = (const float*)d_in[5];
    const float* be   = (const float*)d_in[6];
    const float* sp   = (const float*)d_in[7];
    const float* ut   = (const float*)d_in[8];
    const float* ue   = (const float*)d_in[9];

    float* out = (float*)d_out;

    const size_t n_ltr = (size_t)BT * NTRANS;
    const size_t n_lem = (size_t)BT * NEMISS;
    float* out_ltr;
    float* out_lem;
    if ((size_t)out_size >= 1 + n_ltr + n_lem) {
        out_ltr = out + 1;
        out_lem = out + 1 + n_ltr;
    } else {
        void* p0 = nullptr; void* p1 = nullptr;
        cudaGetSymbolAddress(&p0, g_ltr_scratch);
        cudaGetSymbolAddress(&p1, g_lem_scratch);
        out_ltr = (float*)p0;
        out_lem = (float*)p1;
    }

    cudaFuncSetAttribute(hmma_gemm_kernel, cudaFuncAttributeMaxDynamicSharedMemorySize, HSMEM);

    prep_kernel<<<NB_EMB + NB_W + 1, 256>>>(emb, Wt, We, ut, ue, sp);
    hmma_gemm_kernel<<<dim3(BT/BMH, YEM + NTRANS/BNH), 256, HSMEM>>>(bt_, be, out_ltr, out_lem);
    logev_kernel<<<BT, 256>>>(obs, out_lem);
    scan_kernel<<<64, 32>>>(out_ltr);
    gx_kernel<<<BT, 256>>>(out_ltr, slen);
    fin_kernel<<<1, 256>>>(slen, out);
}

// round 16
// speedup vs baseline: 1.0858x; 1.0858x over previous
#include <cuda_runtime.h>
#include <cuda_bf16.h>
#include <math.h>
#include <stdint.h>

// Problem constants
#define Bn   32
#define Tn   512
#define DEMB 768
#define NSRC 10
#define Hn   16
#define On   16
#define BT   (Bn*Tn)          // 16384
#define NTRANS 256            // H*H
#define NEMISS 2560           // NSRC*H*O

// ---------------- scratch (static device memory; no allocation) ----------------
__device__ __align__(16) float g_logev[BT*Hn];
__device__ __align__(16) float g_alpha[BT*Hn];
__device__ __align__(16) float g_beta [BT*Hn];
__device__ __align__(16) float g_emis [BT];
__device__ __align__(16) float g_tran [BT];
__device__ __align__(16) float g_prior[Bn];
__device__ __align__(16) float g_lsp  [Hn];
__device__ __align__(16) float g_mix_trans[NTRANS];
__device__ __align__(16) float g_mix_emiss[NEMISS];
__device__ __align__(16) float g_ltr_scratch[(size_t)BT * NTRANS];
__device__ __align__(16) float g_lem_scratch[(size_t)BT * NEMISS];

// bf16 split operands for tensor-core GEMM
__device__ __align__(16) __nv_bfloat16 g_Ahi[(size_t)BT*DEMB];
__device__ __align__(16) __nv_bfloat16 g_Alo[(size_t)BT*DEMB];
__device__ __align__(16) __nv_bfloat16 g_Bthi[(size_t)NTRANS*DEMB];
__device__ __align__(16) __nv_bfloat16 g_Btlo[(size_t)NTRANS*DEMB];
__device__ __align__(16) __nv_bfloat16 g_Behi[(size_t)NEMISS*DEMB];
__device__ __align__(16) __nv_bfloat16 g_Belo[(size_t)NEMISS*DEMB];

// ---------------- helpers ----------------
__device__ __forceinline__ uint32_t smem_to_u32(const void* p) {
    uint32_t a;
    asm("{ .reg .u64 t; cvta.to.shared.u64 t, %1; cvt.u32.u64 %0, t; }" : "=r"(a) : "l"(p));
    return a;
}
#define CP_ASYNC16(saddr, gptr) \
    asm volatile("cp.async.cg.shared.global [%0], [%1], 16;" :: "r"(saddr), "l"(gptr))
#define CP_ASYNC4(saddr, gptr) \
    asm volatile("cp.async.ca.shared.global [%0], [%1], 4;" :: "r"(saddr), "l"(gptr))
#define CP_COMMIT() asm volatile("cp.async.commit_group;" ::: "memory")
#define LDSM4(r0,r1,r2,r3, addr) \
    asm volatile("ldmatrix.sync.aligned.m8n8.x4.shared.b16 {%0,%1,%2,%3}, [%4];" \
        : "=r"(r0),"=r"(r1),"=r"(r2),"=r"(r3) : "r"(addr))

__device__ __forceinline__ void mma16816(float* c, const uint32_t* a, uint32_t b0, uint32_t b1) {
    asm volatile(
        "mma.sync.aligned.m16n8k16.row.col.f32.bf16.bf16.f32 "
        "{%0,%1,%2,%3}, {%4,%5,%6,%7}, {%8,%9}, {%0,%1,%2,%3};"
        : "+f"(c[0]), "+f"(c[1]), "+f"(c[2]), "+f"(c[3])
        : "r"(a[0]), "r"(a[1]), "r"(a[2]), "r"(a[3]), "r"(b0), "r"(b1));
}

__device__ __forceinline__ void split_bf16(float x, __nv_bfloat16& h, __nv_bfloat16& l) {
    h = __float2bfloat16_rn(x);
    l = __float2bfloat16_rn(x - __bfloat162float(h));
}

// ---------------- merged prep: emb split + weight transpose/split + tables ------
#define NB_EMB ((BT*DEMB/4 + 255)/256)                    // 12288
#define NB_W   (((NTRANS+NEMISS)*DEMB + 255)/256)         // 8448
__global__ __launch_bounds__(256)
void prep_kernel(const float* __restrict__ emb,
                 const float* __restrict__ Wt, const float* __restrict__ We,
                 const float* __restrict__ ut, const float* __restrict__ ue,
                 const float* __restrict__ sp) {
    int blk = blockIdx.x;
    int tid = threadIdx.x;
    if (blk < NB_EMB) {
        int i = blk * 256 + tid;
        const int N4 = (BT * DEMB) / 4;
        if (i < N4) {
            float4 v = ((const float4*)emb)[i];
            __nv_bfloat16 h0,h1,h2,h3,l0,l1,l2,l3;
            split_bf16(v.x,h0,l0); split_bf16(v.y,h1,l1);
            split_bf16(v.z,h2,l2); split_bf16(v.w,h3,l3);
            __nv_bfloat162* ph = (__nv_bfloat162*)(g_Ahi + (size_t)i*4);
            __nv_bfloat162* pl = (__nv_bfloat162*)(g_Alo + (size_t)i*4);
            ph[0] = __nv_bfloat162(h0,h1); ph[1] = __nv_bfloat162(h2,h3);
            pl[0] = __nv_bfloat162(l0,l1); pl[1] = __nv_bfloat162(l2,l3);
        }
    } else if (blk < NB_EMB + NB_W) {
        int idx = (blk - NB_EMB) * 256 + tid;
        const int NT = NTRANS * DEMB;
        const int NE = NEMISS * DEMB;
        if (idx < NT) {
            int n = idx / DEMB, k = idx % DEMB;
            float x = Wt[(size_t)k * NTRANS + n];
            split_bf16(x, g_Bthi[idx], g_Btlo[idx]);
        } else if (idx < NT + NE) {
            int j = idx - NT;
            int n = j / DEMB, k = j % DEMB;
            int s = n >> 8, e = n & 255;
            float x = We[((size_t)s * DEMB + k) * 256 + e];
            split_bf16(x, g_Behi[j], g_Belo[j]);
        }
    } else {
        if (tid < 16) {
            float v[16]; float m = -1e30f;
            #pragma unroll
            for (int o = 0; o < 16; o++) { v[o] = ut[tid*16+o]; m = fmaxf(m, v[o]); }
            float s = 0.f;
            #pragma unroll
            for (int o = 0; o < 16; o++) s += expf(v[o]-m);
            float inv = 0.5f / s;
            #pragma unroll
            for (int o = 0; o < 16; o++) g_mix_trans[tid*16+o] = expf(v[o]-m) * inv;
        }
        if (tid >= 32 && tid < 32 + NSRC*Hn) {
            int r = tid - 32;
            float v[16]; float m = -1e30f;
            #pragma unroll
            for (int o = 0; o < 16; o++) { v[o] = ue[r*16+o]; m = fmaxf(m, v[o]); }
            float s = 0.f;
            #pragma unroll
            for (int o = 0; o < 16; o++) s += expf(v[o]-m);
            float inv = 0.5f / s;
            #pragma unroll
            for (int o = 0; o < 16; o++) g_mix_emiss[r*16+o] = expf(v[o]-m) * inv;
        }
        if (tid == 255) {
            float m = -1e30f;
            for (int h = 0; h < 16; h++) m = fmaxf(m, sp[h]);
            float s = 0.f;
            for (int h = 0; h < 16; h++) s += expf(sp[h]-m);
            float lse = m + logf(s);
            for (int h = 0; h < 16; h++) g_lsp[h] = sp[h] - lse;
        }
    }
}

// ---------------- merged HMMA GEMM + fused softmax/log-mix epilogue ----------------
#define BMH 128
#define BNH 128
#define BKH 32
#define NCH (DEMB/BKH)        // 24
#define ASTR 80
#define STG_A_HI 0
#define STG_A_LO 10240
#define STG_B_HI 20480
#define STG_B_LO 30720
#define STG_BYTES 40960
#define HSMEM (2*STG_BYTES)   // 81920
#define YEM 20

__global__ __launch_bounds__(256, 2)
void hmma_gemm_kernel(const float* __restrict__ bias_t, const float* __restrict__ bias_e,
                      float* __restrict__ out_t, float* __restrict__ out_e) {
    extern __shared__ __align__(128) char smem[];
    const int tid = threadIdx.x, wid = tid >> 5, lane = tid & 31;
    const int warp_m = wid >> 2, warp_n = wid & 3;
    const int m0 = blockIdx.x * BMH;
    const bool emiss = (blockIdx.y < YEM);
    const int n0 = emiss ? blockIdx.y * BNH : (blockIdx.y - YEM) * BNH;
    const int ncols = emiss ? NEMISS : NTRANS;
    const __nv_bfloat16* __restrict__ Bh = emiss ? g_Behi : g_Bthi;
    const __nv_bfloat16* __restrict__ Bl = emiss ? g_Belo : g_Btlo;
    const float* __restrict__ mixp = emiss ? g_mix_emiss : g_mix_trans;
    const float* __restrict__ bias = emiss ? bias_e : bias_t;
    float* __restrict__ out = emiss ? out_e : out_t;
    const uint32_t sbase = smem_to_u32(smem);

    float bia[8], mx[8];
    {
        int cbase = n0 + warp_n*32 + (lane & 3)*2;
        #pragma unroll
        for (int p = 0; p < 2; p++)
            #pragma unroll
            for (int sel = 0; sel < 2; sel++)
                #pragma unroll
                for (int j = 0; j < 2; j++) {
                    int col = cbase + p*16 + sel*8 + j;
                    bia[p*4+sel*2+j] = bias[col];
                    mx [p*4+sel*2+j] = mixp[col];
                }
    }

    float c[4][4][4];
    #pragma unroll
    for (int a = 0; a < 4; a++)
        #pragma unroll
        for (int b = 0; b < 4; b++)
            #pragma unroll
            for (int q = 0; q < 4; q++) c[a][b][q] = 0.f;

    auto load_chunk = [&](int kc, int stage) {
        const int k0 = kc * BKH;
        uint32_t sm = sbase + stage * STG_BYTES;
        #pragma unroll
        for (int i = 0; i < 2; i++) {
            int seg = i*256 + tid;
            int r = seg >> 2, s = seg & 3;
            size_t goffA = (size_t)(m0 + r) * DEMB + k0 + s*8;
            size_t goffB = (size_t)(n0 + r) * DEMB + k0 + s*8;
            uint32_t soff = (uint32_t)(r * ASTR + s * 16);
            CP_ASYNC16(sm + STG_A_HI + soff, g_Ahi + goffA);
            CP_ASYNC16(sm + STG_A_LO + soff, g_Alo + goffA);
            CP_ASYNC16(sm + STG_B_HI + soff, Bh + goffB);
            CP_ASYNC16(sm + STG_B_LO + soff, Bl + goffB);
        }
        CP_COMMIT();
    };

    auto compute_chunk = [&](int stage) {
        uint32_t sm = sbase + stage * STG_BYTES;
        #pragma unroll
        for (int kk = 0; kk < BKH; kk += 16) {
            uint32_t ah[4][4], al[4][4], bh[2][4], bl[2][4];
            {
                int ar = warp_m*64 + (lane & 15);
                int ac = kk + ((lane >> 4) << 3);
                uint32_t ab = sm + (uint32_t)(ar * ASTR + ac * 2);
                #pragma unroll
                for (int mi = 0; mi < 4; mi++) {
                    LDSM4(ah[mi][0],ah[mi][1],ah[mi][2],ah[mi][3], ab + STG_A_HI + mi*16*ASTR);
                    LDSM4(al[mi][0],al[mi][1],al[mi][2],al[mi][3], ab + STG_A_LO + mi*16*ASTR);
                }
            }
            {
                int br = warp_n*32 + (lane & 7) + ((lane >> 3) & 1)*8;
                int bc = kk + ((lane >> 4) << 3);
                uint32_t bb = sm + (uint32_t)(br * ASTR + bc * 2);
                #pragma unroll
                for (int p = 0; p < 2; p++) {
                    LDSM4(bh[p][0],bh[p][1],bh[p][2],bh[p][3], bb + STG_B_HI + p*16*ASTR);
                    LDSM4(bl[p][0],bl[p][1],bl[p][2],bl[p][3], bb + STG_B_LO + p*16*ASTR);
                }
            }
            #pragma unroll
            for (int mi = 0; mi < 4; mi++)
                #pragma unroll
                for (int p = 0; p < 2; p++) {
                    mma16816(c[mi][2*p+0], ah[mi], bh[p][0], bh[p][2]);
                    mma16816(c[mi][2*p+1], ah[mi], bh[p][1], bh[p][3]);
                }
            #pragma unroll
            for (int mi = 0; mi < 4; mi++)
                #pragma unroll
                for (int p = 0; p < 2; p++) {
                    mma16816(c[mi][2*p+0], ah[mi], bl[p][0], bl[p][2]);
                    mma16816(c[mi][2*p+1], ah[mi], bl[p][1], bl[p][3]);
                }
            #pragma unroll
            for (int mi = 0; mi < 4; mi++)
                #pragma unroll
                for (int p = 0; p < 2; p++) {
                    mma16816(c[mi][2*p+0], al[mi], bh[p][0], bh[p][2]);
                    mma16816(c[mi][2*p+1], al[mi], bh[p][1], bh[p][3]);
                }
        }
    };

    load_chunk(0, 0);
    for (int kc = 0; kc < NCH; kc++) {
        if (kc + 1 < NCH) {
            load_chunk(kc + 1, (kc + 1) & 1);
            asm volatile("cp.async.wait_group 1;" ::: "memory");
        } else {
            asm volatile("cp.async.wait_group 0;" ::: "memory");
        }
        __syncthreads();
        compute_chunk(kc & 1);
        __syncthreads();
    }

    #pragma unroll
    for (int mi = 0; mi < 4; mi++) {
        int rA = m0 + warp_m*64 + mi*16 + (lane >> 2);
        #pragma unroll
        for (int p = 0; p < 2; p++) {
            #pragma unroll
            for (int half = 0; half < 2; half++) {
                float v0 = c[mi][2*p+0][half*2+0] + bia[p*4+0];
                float v1 = c[mi][2*p+0][half*2+1] + bia[p*4+1];
                float v2 = c[mi][2*p+1][half*2+0] + bia[p*4+2];
                float v3 = c[mi][2*p+1][half*2+1] + bia[p*4+3];
                float m = fmaxf(fmaxf(v0, v1), fmaxf(v2, v3));
                m = fmaxf(m, __shfl_xor_sync(0xffffffffu, m, 1));
                m = fmaxf(m, __shfl_xor_sync(0xffffffffu, m, 2));
                float e0 = __expf(v0-m), e1 = __expf(v1-m), e2 = __expf(v2-m), e3 = __expf(v3-m);
                float s = e0 + e1 + e2 + e3;
                s += __shfl_xor_sync(0xffffffffu, s, 1);
                s += __shfl_xor_sync(0xffffffffu, s, 2);
                float inv = 0.5f / s;
                int row = rA + half*8;
                float* orow = out + (size_t)row * ncols + n0 + warp_n*32 + p*16 + (lane & 3)*2;
                orow[0] = __logf(mx[p*4+0] + e0*inv);
                orow[1] = __logf(mx[p*4+1] + e1*inv);
                orow[8] = __logf(mx[p*4+2] + e2*inv);
                orow[9] = __logf(mx[p*4+3] + e3*inv);
            }
        }
    }
}

// ---------------- emission evidence (lane-parallel over o, coalesced) ----------
__global__ __launch_bounds__(256) void logev_kernel(const float* __restrict__ obs,
                                                    const float* __restrict__ lem) {
    int bt = blockIdx.x;
    int tid = threadIdx.x, wid = tid >> 5, lane = tid & 31;
    __shared__ float slog[NSRC][16];
    __shared__ float part[NSRC][16];
    __shared__ float sobs[NSRC][16];
    __shared__ int   lbs[NSRC];
    __shared__ int   entity;

    if (tid < NSRC*16) {
        int s = tid >> 4, o = tid & 15;
        sobs[s][o] = obs[(size_t)bt * NSRC * 16 + tid];
    }
    __syncthreads();
    if (tid < NSRC) {
        int am = 0; float bv = sobs[tid][0];
        for (int k = 1; k < 16; k++) if (sobs[tid][k] > bv) { bv = sobs[tid][k]; am = k; }
        lbs[tid] = am;
    }
    __syncthreads();
    if (tid == 0) { int su = 0; for (int q = 0; q < NSRC; q++) su += lbs[q]; entity = (su > 0); }
    __syncthreads();
    if (tid < NSRC*16) {
        int s = tid >> 4, o = tid & 15;
        float val;
        if (entity && lbs[s] == 0) val = (o == 0) ? 0.01f : (0.99f/16.0f);
        else                       val = sobs[s][o];
        slog[s][o] = logf(val);
    }
    __syncthreads();

    const float* lbase = lem + (size_t)bt * NEMISS;
    int o = lane & 15;
    int hw = lane >> 4;
    #pragma unroll
    for (int it = 0; it < 10; it++) {
        int pi = wid*20 + it*2 + hw;     // 0..159
        int s = pi >> 4, h = pi & 15;
        float x = lbase[s*256 + h*16 + o] + slog[s][o];
        float m = x;
        #pragma unroll
        for (int d = 8; d; d >>= 1) m = fmaxf(m, __shfl_xor_sync(0xffffffffu, m, d));
        float e = __expf(x - m);
        #pragma unroll
        for (int d = 8; d; d >>= 1) e += __shfl_xor_sync(0xffffffffu, e, d);
        if (o == 0) part[s][h] = m + __logf(e);
    }
    __syncthreads();
    if (tid < 16) {
        float t = 0.f;
        #pragma unroll
        for (int q = 0; q < NSRC; q++) t += part[q][tid];
        g_logev[bt*16 + tid] = t;
    }
}

// ---------------- warp-per-chain scans with deep cp.async ring (4B, align-safe) --
#define PFD 8
__global__ __launch_bounds__(32) void scan_kernel(const float* __restrict__ ltr) {
    const unsigned FULL = 0xffffffffu;
    __shared__ __align__(16) float ring_tr[PFD][256];
    __shared__ __align__(16) float ring_ev[PFD][16];
    int lane = threadIdx.x;
    int b = blockIdx.x & 31;
    int j = lane & 15, half = lane >> 4;
    const float* lt_base = ltr + (size_t)b * Tn * 256;   // may be 4B-aligned only
    const float* ev_base = g_logev + (size_t)b * Tn * 16;
    const uint32_t srt = smem_to_u32(ring_tr);
    const uint32_t sre = smem_to_u32(ring_ev);

    auto fetch = [&](int t) {
        uint32_t slot = (uint32_t)(t & (PFD-1));
        const float* src = lt_base + (size_t)t * 256 + lane;
        uint32_t dst = srt + slot * 1024 + lane * 4;
        #pragma unroll
        for (int k = 0; k < 8; k++)
            CP_ASYNC4(dst + k*128, src + k*32);
        if (lane < 16)
            CP_ASYNC4(sre + slot * 64 + lane * 4, ev_base + (size_t)t * 16 + lane);
        CP_COMMIT();
    };

    if (blockIdx.x < 32) {
        // ---- forward: alpha (unnormalized; shift cancels downstream) ----
        float carry = g_lsp[j] + ev_base[j];
        if (lane < 16) g_alpha[(b*Tn)*16 + lane] = carry;
        #pragma unroll
        for (int f = 1; f <= PFD-1; f++) fetch(f);      // prologue
        for (int t = 1; t < Tn; t++) {
            int f = t + PFD - 1;
            if (f < Tn) fetch(f); else CP_COMMIT();
            asm volatile("cp.async.wait_group %0;" :: "n"(PFD-1) : "memory");
            __syncwarp();
            int slot = t & (PFD-1);
            const float* trow = ring_tr[slot];
            float v[8];
            #pragma unroll
            for (int k = 0; k < 8; k++)
                v[k] = __shfl_sync(FULL, carry, half*8 + k) + trow[(half*8+k)*16 + j];
            float m = fmaxf(fmaxf(fmaxf(v[0],v[1]), fmaxf(v[2],v[3])),
                            fmaxf(fmaxf(v[4],v[5]), fmaxf(v[6],v[7])));
            m = fmaxf(m, __shfl_xor_sync(FULL, m, 16));
            float e = 0.f;
            #pragma unroll
            for (int k = 0; k < 8; k++) e += __expf(v[k] - m);
            e += __shfl_xor_sync(FULL, e, 16);
            carry = ring_ev[slot][j] + m + __logf(e);
            if (lane < 16) g_alpha[((size_t)b*Tn + t)*16 + lane] = carry;
            if ((t & 63) == 63) {      // periodic magnitude renorm (exact shift)
                float mm = carry;
                mm = fmaxf(mm, __shfl_xor_sync(FULL, mm, 1));
                mm = fmaxf(mm, __shfl_xor_sync(FULL, mm, 2));
                mm = fmaxf(mm, __shfl_xor_sync(FULL, mm, 4));
                mm = fmaxf(mm, __shfl_xor_sync(FULL, mm, 8));
                carry -= mm;
            }
        }
    } else {
        // ---- backward: beta (unnormalized, matches reference) ----
        int i = lane & 15;
        float carry = 0.f;
        if (lane < 16) g_beta[((size_t)b*Tn + Tn-1)*16 + lane] = 0.f;
        #pragma unroll
        for (int f = 0; f <= PFD-2; f++) fetch(Tn-2 - f);
        for (int t = Tn-2; t >= 0; t--) {
            int f = t - (PFD - 1);
            if (f >= 0) fetch(f); else CP_COMMIT();
            asm volatile("cp.async.wait_group %0;" :: "n"(PFD-1) : "memory");
            __syncwarp();
            int slot = t & (PFD-1);
            float cs = ring_ev[slot][j] + carry;     // ev_t[j] + beta_next[j]
            const float* trow = ring_tr[slot] + i*16 + half*8;
            float4 q0 = *(const float4*)(trow);
            float4 q1 = *(const float4*)(trow + 4);
            float v[8] = {q0.x, q0.y, q0.z, q0.w, q1.x, q1.y, q1.z, q1.w};
            #pragma unroll
            for (int k = 0; k < 8; k++)
                v[k] += __shfl_sync(FULL, cs, half*8 + k);
            float m = fmaxf(fmaxf(fmaxf(v[0],v[1]), fmaxf(v[2],v[3])),
                            fmaxf(fmaxf(v[4],v[5]), fmaxf(v[6],v[7])));
            m = fmaxf(m, __shfl_xor_sync(FULL, m, 16));
            float e = 0.f;
            #pragma unroll
            for (int k = 0; k < 8; k++) e += __expf(v[k] - m);
            e += __shfl_xor_sync(FULL, e, 16);
            carry = m + __logf(e);
            if (lane < 16) g_beta[((size_t)b*Tn + t)*16 + lane] = carry;
        }
    }
}

// ---------------- gamma / xi / per-(b,t) likelihood terms ----------------
__global__ __launch_bounds__(256) void gx_kernel(const float* __restrict__ ltr,
                                                 const int* __restrict__ seqlen) {
    int bt = blockIdx.x, b = bt >> 9, t = bt & (Tn-1), tid = threadIdx.x;
    __shared__ float sa[16], sb[16], se[16], spa[16];
    __shared__ float sw[8];
    int len = seqlen[b];
    int tr = t + (Tn - len); if (tr >= Tn) tr -= Tn;
    if (tid < 16) {
        sa[tid]  = g_alpha[bt*16 + tid];
        sb[tid]  = g_beta[((size_t)b*Tn + tr)*16 + tid];
        se[tid]  = g_logev[bt*16 + tid];
        spa[tid] = (t > 0) ? g_alpha[(bt-1)*16 + tid] : 0.f;
    }
    __syncthreads();
    if (tid == 0) {
        float m = -1e30f;
        for (int h = 0; h < 16; h++) m = fmaxf(m, sa[h]+sb[h]);
        float s = 0.f;
        for (int h = 0; h < 16; h++) s += expf(sa[h]+sb[h]-m);
        float lse = m + logf(s);
        float emis = 0.f, pr = 0.f;
        for (int h = 0; h < 16; h++) {
            float g = expf(sa[h]+sb[h]-lse);
            emis += g * se[h]; pr += g * g_lsp[h];
        }
        g_emis[bt] = emis;
        if (t == 0) g_prior[b] = pr;
    }
    if (t == 0) { if (tid == 0) g_tran[bt] = 0.f; return; }

    float lt = ltr[(size_t)bt*256 + tid];
    float x = lt + spa[tid>>4] + se[tid&15] + sb[tid&15];

    float m = x;
    #pragma unroll
    for (int o = 16; o; o >>= 1) m = fmaxf(m, __shfl_xor_sync(0xffffffffu, m, o));
    if ((tid & 31) == 0) sw[tid>>5] = m;
    __syncthreads();
    m = sw[0];
    #pragma unroll
    for (int wq = 1; wq < 8; wq++) m = fmaxf(m, sw[wq]);
    __syncthreads();
    float e = expf(x - m);
    float s = e;
    #pragma unroll
    for (int o = 16; o; o >>= 1) s += __shfl_xor_sync(0xffffffffu, s, o);
    if ((tid & 31) == 0) sw[tid>>5] = s;
    __syncthreads();
    s = 0.f;
    #pragma unroll
    for (int wq = 0; wq < 8; wq++) s += sw[wq];
    __syncthreads();
    float norm = m + logf(s);
    float term = expf(x - norm) * lt;
    float ts = term;
    #pragma unroll
    for (int o = 16; o; o >>= 1) ts += __shfl_xor_sync(0xffffffffu, ts, o);
    if ((tid & 31) == 0) sw[tid>>5] = ts;
    __syncthreads();
    if (tid == 0) {
        float tot = 0.f;
        #pragma unroll
        for (int wq = 0; wq < 8; wq++) tot += sw[wq];
        g_tran[bt] = tot;
    }
}

// ---------------- final masked reduction -> ll ----------------
__global__ void fin_kernel(const int* __restrict__ seqlen, float* __restrict__ out) {
    __shared__ float sh[256];
    int tid = threadIdx.x;
    float acc = 0.f;
    for (int bt = tid; bt < BT; bt += 256) {
        int b = bt >> 9, t = bt & (Tn-1);
        int len = seqlen[b];
        if (t < len) {
            acc += g_emis[bt];
            if (t >= 1) acc += g_tran[bt];
        }
    }
    if (tid < Bn) acc += g_prior[tid];
    sh[tid] = acc;
    __syncthreads();
    for (int s = 128; s; s >>= 1) {
        if (tid < s) sh[tid] += sh[tid + s];
        __syncthreads();
    }
    if (tid == 0) out[0] = sh[0] / (float)Bn;
}

// ---------------- launch ----------------
extern "C" void kernel_launch(void* const* d_in, const int* in_sizes, int n_in,
                              void* d_out, int out_size) {
    const float* emb  = (const float*)d_in[0];
    const float* obs  = (const float*)d_in[1];
    const int*   slen = (const int*)  d_in[2];
    const float* Wt   = (const float*)d_in[3];
    const float* bt_  = (const float*)d_in[4];
    const float* We   = (const float*)d_in[5];
    const float* be   = (const float*)d_in[6];
    const float* sp   = (const float*)d_in[7];
    const float* ut   = (const float*)d_in[8];
    const float* ue   = (const float*)d_in[9];

    float* out = (float*)d_out;

    const size_t n_ltr = (size_t)BT * NTRANS;
    const size_t n_lem = (size_t)BT * NEMISS;
    float* out_ltr;
    float* out_lem;
    if ((size_t)out_size >= 1 + n_ltr + n_lem) {
        out_ltr = out + 1;
        out_lem = out + 1 + n_ltr;
    } else {
        void* p0 = nullptr; void* p1 = nullptr;
        cudaGetSymbolAddress(&p0, g_ltr_scratch);
        cudaGetSymbolAddress(&p1, g_lem_scratch);
        out_ltr = (float*)p0;
        out_lem = (float*)p1;
    }

    cudaFuncSetAttribute(hmma_gemm_kernel, cudaFuncAttributeMaxDynamicSharedMemorySize, HSMEM);

    prep_kernel<<<NB_EMB + NB_W + 1, 256>>>(emb, Wt, We, ut, ue, sp);
    hmma_gemm_kernel<<<dim3(BT/BMH, YEM + NTRANS/BNH), 256, HSMEM>>>(bt_, be, out_ltr, out_lem);
    logev_kernel<<<BT, 256>>>(obs, out_lem);
    scan_kernel<<<64, 32>>>(out_ltr);
    gx_kernel<<<BT, 256>>>(out_ltr, slen);
    fin_kernel<<<1, 256>>>(slen, out);
}